// round 2
// baseline (speedup 1.0000x reference)
#include <cuda_runtime.h>

#define B_    16
#define C_    256
#define H_    32
#define W_    32
#define N_TOK 16384
#define K_CB  8192
#define ZQ_ELEMS 4194304   // B*H*W*C

// Scratch (allocation-free rule: __device__ globals)
__device__ float g_zflat[N_TOK * C_];          // zp as [N, C], 16 MB
__device__ float g_z2[N_TOK];
__device__ float g_e2[K_CB];
__device__ unsigned long long g_min[N_TOK];    // packed (f32bits(d)<<32)|k
__device__ double g_partial[512];

// ---------------------------------------------------------------------------
// Kernel 1: transpose z [B,C,H,W] -> z_flat [N=B*H*W, C]
// ---------------------------------------------------------------------------
__global__ void k_transpose(const float* __restrict__ z) {
    __shared__ float s[32][33];
    int cb = blockIdx.x;   // c tile (8)
    int h  = blockIdx.y;   // 32
    int b  = blockIdx.z;   // 16
    int tx = threadIdx.x, ty = threadIdx.y;
    // read: c = cb*32+ty, w = tx  (coalesced over tx)
    s[ty][tx] = z[((b * C_ + cb * 32 + ty) * H_ + h) * W_ + tx];
    __syncthreads();
    // write: w = ty, c = cb*32+tx (coalesced over tx)
    g_zflat[(b * 1024 + h * 32 + ty) * C_ + cb * 32 + tx] = s[tx][ty];
}

// ---------------------------------------------------------------------------
// Kernel 2: e2 per code + init g_min
// ---------------------------------------------------------------------------
__global__ void k_e2_init(const float* __restrict__ cbook) {
    int tid = threadIdx.x;
    int gid = blockIdx.x * 256 + tid;
    if (gid < N_TOK) g_min[gid] = ~0ull;
    int k    = blockIdx.x * 8 + (tid >> 5);   // 1024 blocks * 8 warps = 8192
    int lane = tid & 31;
    float s = 0.f;
#pragma unroll
    for (int j = 0; j < 8; j++) {
        float v = cbook[k * C_ + lane + j * 32];
        s += v * v;
    }
    for (int o = 16; o; o >>= 1) s += __shfl_down_sync(0xffffffffu, s, o);
    if (lane == 0) g_e2[k] = s;
}

// ---------------------------------------------------------------------------
// Kernel 3: z2 per token (from z_flat)
// ---------------------------------------------------------------------------
__global__ void k_z2() {
    int tid  = threadIdx.x;
    int tok  = blockIdx.x * 8 + (tid >> 5);   // 2048 blocks * 8 warps = 16384
    int lane = tid & 31;
    float s = 0.f;
#pragma unroll
    for (int j = 0; j < 8; j++) {
        float v = g_zflat[tok * C_ + lane + j * 32];
        s += v * v;
    }
    for (int o = 16; o; o >>= 1) s += __shfl_down_sync(0xffffffffu, s, o);
    if (lane == 0) g_z2[tok] = s;
}

// ---------------------------------------------------------------------------
// Kernel 4: fused distance GEMM + argmin.
// Block tile 128 tokens x 128 codes, 256 threads, 8x8 microtile, K-chunk = 8.
// ---------------------------------------------------------------------------
__global__ __launch_bounds__(256, 2) void k_argmin(const float* __restrict__ cbook) {
    __shared__ float As[8][132];
    __shared__ float Bs[8][132];
    __shared__ unsigned long long scand[128];

    int tid = threadIdx.x;
    int n0 = blockIdx.x * 128;   // code tile   (64 tiles)
    int m0 = blockIdx.y * 128;   // token tile  (128 tiles)
    int row = tid >> 1;          // 0..127
    int kq  = (tid & 1) * 4;     // 0 or 4
    int tr = tid >> 4;           // 0..15 (token group)
    int tc = tid & 15;           // 0..15 (code group)

    if (tid < 128) scand[tid] = ~0ull;

    float acc[8][8];
#pragma unroll
    for (int i = 0; i < 8; i++)
#pragma unroll
        for (int j = 0; j < 8; j++) acc[i][j] = 0.f;

    float4 va = *(const float4*)&g_zflat[(m0 + row) * C_ + kq];
    float4 vb = *(const float4*)&cbook [(n0 + row) * C_ + kq];

    for (int kt = 0; kt < 32; kt++) {
        __syncthreads();
        As[kq + 0][row] = va.x; As[kq + 1][row] = va.y;
        As[kq + 2][row] = va.z; As[kq + 3][row] = va.w;
        Bs[kq + 0][row] = vb.x; Bs[kq + 1][row] = vb.y;
        Bs[kq + 2][row] = vb.z; Bs[kq + 3][row] = vb.w;
        __syncthreads();
        if (kt < 31) {  // prefetch next chunk under compute
            va = *(const float4*)&g_zflat[(m0 + row) * C_ + (kt + 1) * 8 + kq];
            vb = *(const float4*)&cbook [(n0 + row) * C_ + (kt + 1) * 8 + kq];
        }
#pragma unroll
        for (int kc = 0; kc < 8; kc++) {
            float4 a0 = *(const float4*)&As[kc][tr * 8];
            float4 a1 = *(const float4*)&As[kc][tr * 8 + 4];
            float4 b0 = *(const float4*)&Bs[kc][tc * 8];
            float4 b1 = *(const float4*)&Bs[kc][tc * 8 + 4];
            float a[8] = {a0.x, a0.y, a0.z, a0.w, a1.x, a1.y, a1.z, a1.w};
            float b[8] = {b0.x, b0.y, b0.z, b0.w, b1.x, b1.y, b1.z, b1.w};
#pragma unroll
            for (int i = 0; i < 8; i++)
#pragma unroll
                for (int j = 0; j < 8; j++) acc[i][j] += a[i] * b[j];
        }
    }

    // Epilogue: d = fl(fl(z2 + e2) - 2*acc); pack with index; first-min ties.
    float z2r[8], e2r[8];
#pragma unroll
    for (int i = 0; i < 8; i++) z2r[i] = g_z2[m0 + tr * 8 + i];
#pragma unroll
    for (int j = 0; j < 8; j++) e2r[j] = g_e2[n0 + tc * 8 + j];

#pragma unroll
    for (int i = 0; i < 8; i++) {
        unsigned long long best = ~0ull;
#pragma unroll
        for (int j = 0; j < 8; j++) {
            float s = __fadd_rn(z2r[i], e2r[j]);
            float d = __fadd_rn(s, -2.0f * acc[i][j]);   // 2*acc exact; single rounding
            unsigned long long p =
                ((unsigned long long)__float_as_uint(d) << 32) |
                (unsigned)(n0 + tc * 8 + j);
            if (p < best) best = p;
        }
        atomicMin(&scand[tr * 8 + i], best);
    }
    __syncthreads();
    if (tid < 128) atomicMin(&g_min[m0 + tid], scand[tid]);
}

// ---------------------------------------------------------------------------
// Kernel 5: gather z_q with the faithful scramble, write z_q_st, accumulate
// squared error (deterministic block partials in double).
// out[b,h,w,c] = codebook[idx(b*1024 + w*32 + (c>>3))][((c&7)<<5)|h]
// ---------------------------------------------------------------------------
__global__ void k_output(const float* __restrict__ cbook, float* __restrict__ out) {
    __shared__ float srow[256];
    __shared__ double sred[256];
    int t  = threadIdx.x;
    int bw = blockIdx.x;          // 512 blocks
    int b = bw >> 5, w = bw & 31;
    int gam = t & 7, h = t >> 3;
    double local = 0.0;

    for (int q = 0; q < 32; q++) {
        int np = b * 1024 + w * 32 + q;
        unsigned idx = (unsigned)(g_min[np] & 0xffffffffu);
        __syncthreads();
        srow[t] = cbook[idx * C_ + t];      // coalesced codebook row
        __syncthreads();
        int c  = q * 8 + gam;
        int cc = (gam << 5) | h;
        float zq = srow[cc];
        float zp = g_zflat[(b * 1024 + h * 32 + w) * C_ + c];
        out[((b * 32 + h) * 32 + w) * C_ + c] = zq;
        float df = zp - zq;
        local += (double)df * (double)df;
    }
    sred[t] = local;
    __syncthreads();
    for (int o = 128; o; o >>= 1) {
        if (t < o) sred[t] += sred[t + o];
        __syncthreads();
    }
    if (t == 0) g_partial[bw] = sred[0];
}

// ---------------------------------------------------------------------------
// Kernel 6: final loss + indices
// ---------------------------------------------------------------------------
__global__ void k_final(float* __restrict__ out, int has_loss, int has_idx) {
    __shared__ double sr[256];
    int t   = threadIdx.x;
    int gid = blockIdx.x * 256 + t;
    if (has_idx && gid < N_TOK)
        out[ZQ_ELEMS + 1 + gid] = (float)(unsigned)(g_min[gid] & 0xffffffffu);
    if (has_loss && blockIdx.x == 0) {
        sr[t] = g_partial[t] + g_partial[t + 256];
        __syncthreads();
        for (int o = 128; o; o >>= 1) {
            if (t < o) sr[t] += sr[t + o];
            __syncthreads();
        }
        if (t == 0) out[ZQ_ELEMS] = (float)(1.25 * sr[0] / (double)ZQ_ELEMS);
    }
}

// ---------------------------------------------------------------------------
extern "C" void kernel_launch(void* const* d_in, const int* in_sizes, int n_in,
                              void* d_out, int out_size) {
    const float* z  = (const float*)d_in[0];   // [16,256,32,32]
    const float* cb = (const float*)d_in[1];   // [8192,256]
    float* out = (float*)d_out;

    k_transpose<<<dim3(8, 32, 16), dim3(32, 32)>>>(z);
    k_e2_init<<<1024, 256>>>(cb);
    k_z2<<<2048, 256>>>();
    k_argmin<<<dim3(64, 128), 256>>>(cb);
    if (out_size >= ZQ_ELEMS) {                 // z_q_st present (fixed: was N_TOK*C_*B_)
        k_output<<<512, 256>>>(cb, out);
    }
    int has_loss = (out_size >= ZQ_ELEMS + 1) ? 1 : 0;
    int has_idx  = (out_size >= ZQ_ELEMS + 1 + N_TOK) ? 1 : 0;
    k_final<<<64, 256>>>(out, has_loss, has_idx);
}

// round 3
// speedup vs baseline: 1.0012x; 1.0012x over previous
#include <cuda_runtime.h>

#define B_    16
#define C_    256
#define H_    32
#define W_    32
#define N_TOK 16384
#define K_CB  8192
#define ZQ_ELEMS 4194304   // B*H*W*C

// Scratch (allocation-free rule: __device__ globals)
__device__ float g_zflat[N_TOK * C_];          // zp as [N, C], 16 MB
__device__ float g_z2[N_TOK];
__device__ float g_e2[K_CB];
__device__ unsigned long long g_min[N_TOK];    // packed (f32bits(d)<<32)|k
__device__ double g_partial[512];

// ---------------------------------------------------------------------------
// Kernel 1: transpose z [B,C,H,W] -> z_flat [N=B*H*W, C]
// ---------------------------------------------------------------------------
__global__ void k_transpose(const float* __restrict__ z) {
    __shared__ float s[32][33];
    int cb = blockIdx.x;   // c tile (8)
    int h  = blockIdx.y;   // 32
    int b  = blockIdx.z;   // 16
    int tx = threadIdx.x, ty = threadIdx.y;
    // read: c = cb*32+ty, w = tx  (coalesced over tx)
    s[ty][tx] = z[((b * C_ + cb * 32 + ty) * H_ + h) * W_ + tx];
    __syncthreads();
    // write: w = ty, c = cb*32+tx (coalesced over tx)
    g_zflat[(b * 1024 + h * 32 + ty) * C_ + cb * 32 + tx] = s[tx][ty];
}

// ---------------------------------------------------------------------------
// Kernel 2: e2 per code + init g_min
// ---------------------------------------------------------------------------
__global__ void k_e2_init(const float* __restrict__ cbook) {
    int tid = threadIdx.x;
    int gid = blockIdx.x * 256 + tid;
    if (gid < N_TOK) g_min[gid] = ~0ull;
    int k    = blockIdx.x * 8 + (tid >> 5);   // 1024 blocks * 8 warps = 8192
    int lane = tid & 31;
    float s = 0.f;
#pragma unroll
    for (int j = 0; j < 8; j++) {
        float v = cbook[k * C_ + lane + j * 32];
        s += v * v;
    }
    for (int o = 16; o; o >>= 1) s += __shfl_down_sync(0xffffffffu, s, o);
    if (lane == 0) g_e2[k] = s;
}

// ---------------------------------------------------------------------------
// Kernel 3: z2 per token (from z_flat)
// ---------------------------------------------------------------------------
__global__ void k_z2() {
    int tid  = threadIdx.x;
    int tok  = blockIdx.x * 8 + (tid >> 5);   // 2048 blocks * 8 warps = 16384
    int lane = tid & 31;
    float s = 0.f;
#pragma unroll
    for (int j = 0; j < 8; j++) {
        float v = g_zflat[tok * C_ + lane + j * 32];
        s += v * v;
    }
    for (int o = 16; o; o >>= 1) s += __shfl_down_sync(0xffffffffu, s, o);
    if (lane == 0) g_z2[tok] = s;
}

// ---------------------------------------------------------------------------
// Kernel 4: fused distance GEMM + argmin.
// Block tile 128 tokens x 128 codes, 256 threads, 8x8 microtile, K-chunk = 8.
// ---------------------------------------------------------------------------
__global__ __launch_bounds__(256, 2) void k_argmin(const float* __restrict__ cbook) {
    __shared__ float As[8][132];
    __shared__ float Bs[8][132];
    __shared__ unsigned long long scand[128];

    int tid = threadIdx.x;
    int n0 = blockIdx.x * 128;   // code tile   (64 tiles)
    int m0 = blockIdx.y * 128;   // token tile  (128 tiles)
    int row = tid >> 1;          // 0..127
    int kq  = (tid & 1) * 4;     // 0 or 4
    int tr = tid >> 4;           // 0..15 (token group)
    int tc = tid & 15;           // 0..15 (code group)

    if (tid < 128) scand[tid] = ~0ull;

    float acc[8][8];
#pragma unroll
    for (int i = 0; i < 8; i++)
#pragma unroll
        for (int j = 0; j < 8; j++) acc[i][j] = 0.f;

    float4 va = *(const float4*)&g_zflat[(m0 + row) * C_ + kq];
    float4 vb = *(const float4*)&cbook [(n0 + row) * C_ + kq];

    for (int kt = 0; kt < 32; kt++) {
        __syncthreads();
        As[kq + 0][row] = va.x; As[kq + 1][row] = va.y;
        As[kq + 2][row] = va.z; As[kq + 3][row] = va.w;
        Bs[kq + 0][row] = vb.x; Bs[kq + 1][row] = vb.y;
        Bs[kq + 2][row] = vb.z; Bs[kq + 3][row] = vb.w;
        __syncthreads();
        if (kt < 31) {  // prefetch next chunk under compute
            va = *(const float4*)&g_zflat[(m0 + row) * C_ + (kt + 1) * 8 + kq];
            vb = *(const float4*)&cbook [(n0 + row) * C_ + (kt + 1) * 8 + kq];
        }
#pragma unroll
        for (int kc = 0; kc < 8; kc++) {
            float4 a0 = *(const float4*)&As[kc][tr * 8];
            float4 a1 = *(const float4*)&As[kc][tr * 8 + 4];
            float4 b0 = *(const float4*)&Bs[kc][tc * 8];
            float4 b1 = *(const float4*)&Bs[kc][tc * 8 + 4];
            float a[8] = {a0.x, a0.y, a0.z, a0.w, a1.x, a1.y, a1.z, a1.w};
            float b[8] = {b0.x, b0.y, b0.z, b0.w, b1.x, b1.y, b1.z, b1.w};
#pragma unroll
            for (int i = 0; i < 8; i++)
#pragma unroll
                for (int j = 0; j < 8; j++) acc[i][j] += a[i] * b[j];
        }
    }

    // Epilogue: d = fl(fl(z2 + e2) - 2*acc); pack with index; first-min ties.
    float z2r[8], e2r[8];
#pragma unroll
    for (int i = 0; i < 8; i++) z2r[i] = g_z2[m0 + tr * 8 + i];
#pragma unroll
    for (int j = 0; j < 8; j++) e2r[j] = g_e2[n0 + tc * 8 + j];

#pragma unroll
    for (int i = 0; i < 8; i++) {
        unsigned long long best = ~0ull;
#pragma unroll
        for (int j = 0; j < 8; j++) {
            float s = __fadd_rn(z2r[i], e2r[j]);
            float d = __fadd_rn(s, -2.0f * acc[i][j]);   // 2*acc exact; single rounding
            unsigned long long p =
                ((unsigned long long)__float_as_uint(d) << 32) |
                (unsigned)(n0 + tc * 8 + j);
            if (p < best) best = p;
        }
        atomicMin(&scand[tr * 8 + i], best);
    }
    __syncthreads();
    if (tid < 128) atomicMin(&g_min[m0 + tid], scand[tid]);
}

// ---------------------------------------------------------------------------
// Kernel 5: gather z_q with the faithful scramble, write z_q_st, accumulate
// squared error (deterministic block partials in double).
// out[b,h,w,c] = codebook[idx(b*1024 + w*32 + (c>>3))][((c&7)<<5)|h]
// ---------------------------------------------------------------------------
__global__ void k_output(const float* __restrict__ cbook, float* __restrict__ out) {
    __shared__ float srow[256];
    __shared__ double sred[256];
    int t  = threadIdx.x;
    int bw = blockIdx.x;          // 512 blocks
    int b = bw >> 5, w = bw & 31;
    int gam = t & 7, h = t >> 3;
    double local = 0.0;

    for (int q = 0; q < 32; q++) {
        int np = b * 1024 + w * 32 + q;
        unsigned idx = (unsigned)(g_min[np] & 0xffffffffu);
        __syncthreads();
        srow[t] = cbook[idx * C_ + t];      // coalesced codebook row
        __syncthreads();
        int c  = q * 8 + gam;
        int cc = (gam << 5) | h;
        float zq = srow[cc];
        float zp = g_zflat[(b * 1024 + h * 32 + w) * C_ + c];
        out[((b * 32 + h) * 32 + w) * C_ + c] = zq;
        float df = zp - zq;
        local += (double)df * (double)df;
    }
    sred[t] = local;
    __syncthreads();
    for (int o = 128; o; o >>= 1) {
        if (t < o) sred[t] += sred[t + o];
        __syncthreads();
    }
    if (t == 0) g_partial[bw] = sred[0];
}

// ---------------------------------------------------------------------------
// Kernel 6: final loss + indices
// ---------------------------------------------------------------------------
__global__ void k_final(float* __restrict__ out, int has_loss, int has_idx) {
    __shared__ double sr[256];
    int t   = threadIdx.x;
    int gid = blockIdx.x * 256 + t;
    if (has_idx && gid < N_TOK)
        out[ZQ_ELEMS + 1 + gid] = (float)(unsigned)(g_min[gid] & 0xffffffffu);
    if (has_loss && blockIdx.x == 0) {
        sr[t] = g_partial[t] + g_partial[t + 256];
        __syncthreads();
        for (int o = 128; o; o >>= 1) {
            if (t < o) sr[t] += sr[t + o];
            __syncthreads();
        }
        if (t == 0) out[ZQ_ELEMS] = (float)(1.25 * sr[0] / (double)ZQ_ELEMS);
    }
}

// ---------------------------------------------------------------------------
extern "C" void kernel_launch(void* const* d_in, const int* in_sizes, int n_in,
                              void* d_out, int out_size) {
    const float* z  = (const float*)d_in[0];   // [16,256,32,32]
    const float* cb = (const float*)d_in[1];   // [8192,256]
    float* out = (float*)d_out;

    k_transpose<<<dim3(8, 32, 16), dim3(32, 32)>>>(z);
    k_e2_init<<<1024, 256>>>(cb);
    k_z2<<<2048, 256>>>();
    k_argmin<<<dim3(64, 128), 256>>>(cb);
    if (out_size >= ZQ_ELEMS) {                 // z_q_st present (fixed: was N_TOK*C_*B_)
        k_output<<<512, 256>>>(cb, out);
    }
    int has_loss = (out_size >= ZQ_ELEMS + 1) ? 1 : 0;
    int has_idx  = (out_size >= ZQ_ELEMS + 1 + N_TOK) ? 1 : 0;
    k_final<<<64, 256>>>(out, has_loss, has_idx);
}

// round 7
// speedup vs baseline: 3.2687x; 3.2649x over previous
#include <cuda_runtime.h>
#include <cuda_bf16.h>
#include <cstdint>

#define C_    256
#define N_TOK 16384
#define K_CB  8192
#define ZQ_ELEMS 4194304
#define CAP   512
#define MARGIN 4e-4f

// ---------------- scratch ---------------------------------------------------
__device__ float g_zflat[N_TOK * C_];
__device__ float g_z2[N_TOK];
__device__ float g_e2[K_CB];
__device__ unsigned long long g_min[N_TOK];
__device__ double g_partial[512];
__device__ __nv_bfloat16 g_zbf[N_TOK * C_];
__device__ __nv_bfloat16 g_cbbf[K_CB * C_];
__device__ int g_ccount[N_TOK];
__device__ int g_cand[N_TOK * CAP];

// ---------------- helpers ---------------------------------------------------
__device__ __forceinline__ uint32_t smem_u32(const void* p) {
    uint32_t a;
    asm("{ .reg .u64 t; cvta.to.shared.u64 t, %1; cvt.u32.u64 %0, t; }" : "=r"(a) : "l"(p));
    return a;
}
__device__ __forceinline__ unsigned encf(float f) {
    unsigned u = __float_as_uint(f);
    return (u & 0x80000000u) ? ~u : (u | 0x80000000u);
}
__device__ __forceinline__ float decf(unsigned e) {
    unsigned u = (e & 0x80000000u) ? (e ^ 0x80000000u) : ~e;
    return __uint_as_float(u);
}
#define LDM_X4(r0, r1, r2, r3, a) \
    asm volatile("ldmatrix.sync.aligned.m8n8.x4.shared.b16 {%0,%1,%2,%3}, [%4];" \
                 : "=r"(r0), "=r"(r1), "=r"(r2), "=r"(r3) : "r"(a))
#define MMA16816(c, a, b0, b1) \
    asm volatile("mma.sync.aligned.m16n8k16.row.col.f32.bf16.bf16.f32 " \
                 "{%0,%1,%2,%3}, {%4,%5,%6,%7}, {%8,%9}, {%0,%1,%2,%3};" \
                 : "+f"((c)[0]), "+f"((c)[1]), "+f"((c)[2]), "+f"((c)[3]) \
                 : "r"((a)[0]), "r"((a)[1]), "r"((a)[2]), "r"((a)[3]), "r"(b0), "r"(b1))

// ---------------------------------------------------------------------------
__global__ void k_transpose(const float* __restrict__ z) {
    __shared__ float s[32][33];
    int cb = blockIdx.x, h = blockIdx.y, b = blockIdx.z;
    int tx = threadIdx.x, ty = threadIdx.y;
    s[ty][tx] = z[((b * C_ + cb * 32 + ty) * 32 + h) * 32 + tx];
    __syncthreads();
    float v = s[tx][ty];
    int idx = (b * 1024 + h * 32 + ty) * C_ + cb * 32 + tx;
    g_zflat[idx] = v;
    g_zbf[idx] = __float2bfloat16_rn(v);
}

__global__ void k_e2_init(const float* __restrict__ cbook) {
    int tid = threadIdx.x;
    int gid = blockIdx.x * 256 + tid;
    if (gid < N_TOK) { g_min[gid] = ~0ull; g_ccount[gid] = 0; }
    int k = blockIdx.x * 8 + (tid >> 5), lane = tid & 31;
    float s = 0.f;
#pragma unroll
    for (int j = 0; j < 8; j++) {
        float v = cbook[k * C_ + lane + j * 32];
        g_cbbf[k * C_ + lane + j * 32] = __float2bfloat16_rn(v);
        s += v * v;
    }
    for (int o = 16; o; o >>= 1) s += __shfl_down_sync(0xffffffffu, s, o);
    if (lane == 0) g_e2[k] = s;
}

__global__ void k_z2() {
    int tid = threadIdx.x;
    int tok = blockIdx.x * 8 + (tid >> 5), lane = tid & 31;
    float s = 0.f;
#pragma unroll
    for (int j = 0; j < 8; j++) { float v = g_zflat[tok * C_ + lane + j * 32]; s += v * v; }
    for (int o = 16; o; o >>= 1) s += __shfl_down_sync(0xffffffffu, s, o);
    if (lane == 0) g_z2[tok] = s;
}

// ---------------------------------------------------------------------------
// Filter GEMM via mma.sync bf16: per CTA 128 tokens vs 8192 codes (32x256).
// smem layout (dynamic): A[128][264] bf16 @0, B[256][264] bf16 @67584,
//                        e2s[256] f32 @202752, rm[128] u32 @203776.
// ---------------------------------------------------------------------------
#define ASTRIDE 528u            // 264 bf16 per row (8-half pad: conflict-free)
#define OFF_A   0u
#define OFF_B   67584u
#define OFF_E2  202752u
#define OFF_RM  203776u
#define SM_TOT  204288u

__global__ __launch_bounds__(256, 1) void k_gemm() {
    extern __shared__ char smem[];
    uint32_t sb = smem_u32(smem);
    int tid = threadIdx.x, wid = tid >> 5, lane = tid & 31;
    int g = lane >> 2, tg = lane & 3;
    int wm = wid >> 2, wn = wid & 3;          // 2 x 4 warp grid
    int m0 = blockIdx.x * 128;
    float*    e2s = (float*)(smem + OFF_E2);
    unsigned* rm  = (unsigned*)(smem + OFF_RM);

    // load A tile (128 x 256 bf16), plain row layout with padded stride
    for (int i = tid; i < 4096; i += 256) {
        int row = i >> 5, c8 = (i & 31) * 8;
        *(uint4*)(smem + OFF_A + row * ASTRIDE + c8 * 2) =
            *(const uint4*)&g_zbf[(m0 + row) * C_ + c8];
    }
    if (tid < 128) rm[tid] = 0xFFFFFFFFu;

    // per-lane ldmatrix A address base: matrices (m0-7,k0-7),(m8-15,k0-7),(m0-7,k8-15),(m8-15,k8-15)
    int arow = (lane & 7) + ((lane >> 3) & 1) * 8;
    int akb  = (lane >> 4) & 1;
    uint32_t aBase = sb + OFF_A + (uint32_t)(wm * 64 + arow) * ASTRIDE + (uint32_t)akb * 16;
    // per-lane B scalar base: row = wn*64 + g, col halves = tg*2
    uint32_t bLane = OFF_B + (uint32_t)(wn * 64 + g) * ASTRIDE + (uint32_t)tg * 4;

    for (int chunk = 0; chunk < 32; chunk++) {
        __syncthreads();   // protect B/e2s from pass2 readers of previous chunk
        // load B chunk (256 codes x 256 bf16) + e2
        for (int i = tid; i < 8192; i += 256) {
            int row = i >> 5, c8 = (i & 31) * 8;
            *(uint4*)(smem + OFF_B + row * ASTRIDE + c8 * 2) =
                *(const uint4*)&g_cbbf[(chunk * 256 + row) * C_ + c8];
        }
        if (tid < 256) e2s[tid] = g_e2[chunk * 256 + tid];
        __syncthreads();

        float acc[4][8][4];
#pragma unroll
        for (int mt = 0; mt < 4; mt++)
#pragma unroll
            for (int nt = 0; nt < 8; nt++)
#pragma unroll
                for (int c = 0; c < 4; c++) acc[mt][nt][c] = 0.f;

#pragma unroll
        for (int ks = 0; ks < 16; ks++) {
            uint32_t a[4][4];
#pragma unroll
            for (int mt = 0; mt < 4; mt++)
                LDM_X4(a[mt][0], a[mt][1], a[mt][2], a[mt][3],
                       aBase + (uint32_t)(mt * 16) * ASTRIDE + (uint32_t)ks * 32);
#pragma unroll
            for (int nt = 0; nt < 8; nt++) {
                uint32_t boff = bLane + (uint32_t)(nt * 8) * ASTRIDE + (uint32_t)ks * 32;
                uint32_t b0 = *(const uint32_t*)(smem + boff);
                uint32_t b1 = *(const uint32_t*)(smem + boff + 16);
#pragma unroll
                for (int mt = 0; mt < 4; mt++) MMA16816(acc[mt][nt], a[mt], b0, b1);
            }
        }

        // pass 1: per-token chunk minima -> shared rm (order-preserving uint)
#pragma unroll
        for (int mt = 0; mt < 4; mt++) {
            unsigned e0 = 0xFFFFFFFFu, e1 = 0xFFFFFFFFu;
#pragma unroll
            for (int nt = 0; nt < 8; nt++) {
                int nl = wn * 64 + nt * 8 + tg * 2;
                float m00 = __fmaf_rn(-2.f, acc[mt][nt][0], e2s[nl]);
                float m01 = __fmaf_rn(-2.f, acc[mt][nt][1], e2s[nl + 1]);
                float m10 = __fmaf_rn(-2.f, acc[mt][nt][2], e2s[nl]);
                float m11 = __fmaf_rn(-2.f, acc[mt][nt][3], e2s[nl + 1]);
                e0 = min(e0, min(encf(m00), encf(m01)));
                e1 = min(e1, min(encf(m10), encf(m11)));
            }
            e0 = min(e0, __shfl_xor_sync(0xffffffffu, e0, 1));
            e0 = min(e0, __shfl_xor_sync(0xffffffffu, e0, 2));
            e1 = min(e1, __shfl_xor_sync(0xffffffffu, e1, 1));
            e1 = min(e1, __shfl_xor_sync(0xffffffffu, e1, 2));
            if (tg == 0) {
                atomicMin(&rm[wm * 64 + mt * 16 + g], e0);
                atomicMin(&rm[wm * 64 + mt * 16 + 8 + g], e1);
            }
        }
        __syncthreads();

        // pass 2: emit candidates within MARGIN of token min-so-far
#pragma unroll
        for (int mt = 0; mt < 4; mt++) {
            int r0 = wm * 64 + mt * 16 + g, r1 = r0 + 8;
            float th0 = decf(rm[r0]) + MARGIN;
            float th1 = decf(rm[r1]) + MARGIN;
            int tok0 = m0 + r0, tok1 = m0 + r1;
#pragma unroll
            for (int nt = 0; nt < 8; nt++) {
                int nl = wn * 64 + nt * 8 + tg * 2;
                int code = chunk * 256 + nl;
                float m00 = __fmaf_rn(-2.f, acc[mt][nt][0], e2s[nl]);
                float m01 = __fmaf_rn(-2.f, acc[mt][nt][1], e2s[nl + 1]);
                float m10 = __fmaf_rn(-2.f, acc[mt][nt][2], e2s[nl]);
                float m11 = __fmaf_rn(-2.f, acc[mt][nt][3], e2s[nl + 1]);
                if (m00 < th0) { int s = atomicAdd(&g_ccount[tok0], 1); if (s < CAP) g_cand[tok0 * CAP + s] = code; }
                if (m01 < th0) { int s = atomicAdd(&g_ccount[tok0], 1); if (s < CAP) g_cand[tok0 * CAP + s] = code + 1; }
                if (m10 < th1) { int s = atomicAdd(&g_ccount[tok1], 1); if (s < CAP) g_cand[tok1 * CAP + s] = code; }
                if (m11 < th1) { int s = atomicAdd(&g_ccount[tok1], 1); if (s < CAP) g_cand[tok1 * CAP + s] = code + 1; }
            }
        }
    }
}

// ---------------------------------------------------------------------------
// Exact rescue: block per token, warp per candidate (fp32, R2 numerics)
// ---------------------------------------------------------------------------
__global__ __launch_bounds__(256, 4) void k_exact(const float* __restrict__ cbook) {
    __shared__ float zrow[256];
    int tok = blockIdx.x;
    int tid = threadIdx.x, wid = tid >> 5, lane = tid & 31;
    zrow[tid] = g_zflat[tok * C_ + tid];
    int cnt = g_ccount[tok]; if (cnt > CAP) cnt = CAP;
    float z2 = g_z2[tok];
    __syncthreads();
    for (int slot = wid; slot < cnt; slot += 8) {
        int code = g_cand[tok * CAP + slot];
        float s = 0.f;
#pragma unroll
        for (int j = 0; j < 8; j++)
            s += zrow[lane + 32 * j] * cbook[code * C_ + lane + 32 * j];
        for (int o = 16; o; o >>= 1) s += __shfl_down_sync(0xffffffffu, s, o);
        if (lane == 0) {
            float sz = __fadd_rn(z2, g_e2[code]);
            float d = __fadd_rn(sz, -2.0f * s);
            unsigned long long p = ((unsigned long long)__float_as_uint(d) << 32) | (unsigned)code;
            atomicMin(&g_min[tok], p);
        }
    }
}

// ---------------------------------------------------------------------------
__global__ void k_output(const float* __restrict__ cbook, float* __restrict__ out) {
    __shared__ float srow[256];
    __shared__ double sred[256];
    int t = threadIdx.x, bw = blockIdx.x;
    int b = bw >> 5, w = bw & 31;
    int gam = t & 7, h = t >> 3;
    double local = 0.0;
    for (int q = 0; q < 32; q++) {
        int np = b * 1024 + w * 32 + q;
        unsigned idx = (unsigned)(g_min[np] & 0xffffffffu);
        __syncthreads();
        srow[t] = cbook[idx * C_ + t];
        __syncthreads();
        int c = q * 8 + gam, cc = (gam << 5) | h;
        float zq = srow[cc];
        float zp = g_zflat[(b * 1024 + h * 32 + w) * C_ + c];
        out[((b * 32 + h) * 32 + w) * C_ + c] = zq;
        float df = zp - zq;
        local += (double)df * (double)df;
    }
    sred[t] = local;
    __syncthreads();
    for (int o = 128; o; o >>= 1) { if (t < o) sred[t] += sred[t + o]; __syncthreads(); }
    if (t == 0) g_partial[bw] = sred[0];
}

__global__ void k_final(float* __restrict__ out, int has_loss, int has_idx) {
    __shared__ double sr[256];
    int t = threadIdx.x, gid = blockIdx.x * 256 + t;
    if (has_idx && gid < N_TOK)
        out[ZQ_ELEMS + 1 + gid] = (float)(unsigned)(g_min[gid] & 0xffffffffu);
    if (has_loss && blockIdx.x == 0) {
        sr[t] = g_partial[t] + g_partial[t + 256];
        __syncthreads();
        for (int o = 128; o; o >>= 1) { if (t < o) sr[t] += sr[t + o]; __syncthreads(); }
        if (t == 0) out[ZQ_ELEMS] = (float)(1.25 * sr[0] / (double)ZQ_ELEMS);
    }
}

// ---------------------------------------------------------------------------
extern "C" void kernel_launch(void* const* d_in, const int* in_sizes, int n_in,
                              void* d_out, int out_size) {
    const float* z  = (const float*)d_in[0];
    const float* cb = (const float*)d_in[1];
    float* out = (float*)d_out;

    cudaFuncSetAttribute(k_gemm, cudaFuncAttributeMaxDynamicSharedMemorySize, SM_TOT);

    k_transpose<<<dim3(8, 32, 16), dim3(32, 32)>>>(z);
    k_e2_init<<<1024, 256>>>(cb);
    k_z2<<<2048, 256>>>();
    k_gemm<<<128, 256, SM_TOT>>>();
    k_exact<<<N_TOK, 256>>>(cb);
    if (out_size >= ZQ_ELEMS) k_output<<<512, 256>>>(cb, out);
    int has_loss = (out_size >= ZQ_ELEMS + 1) ? 1 : 0;
    int has_idx  = (out_size >= ZQ_ELEMS + 1 + N_TOK) ? 1 : 0;
    k_final<<<64, 256>>>(out, has_loss, has_idx);
}

// round 9
// speedup vs baseline: 3.2948x; 1.0080x over previous
#include <cuda_runtime.h>
#include <cuda_bf16.h>
#include <cstdint>

#define C_    256
#define N_TOK 16384
#define K_CB  8192
#define ZQ_ELEMS 4194304
#define CAP   512
#define MARGIN 4e-4f

// ---------------- scratch ---------------------------------------------------
__device__ float g_zflat[N_TOK * C_];
__device__ float g_z2[N_TOK];
__device__ float g_e2[K_CB];
__device__ unsigned long long g_min[N_TOK];
__device__ double g_partial[512];
__device__ __nv_bfloat16 g_zbf[N_TOK * C_];
__device__ __nv_bfloat16 g_cbbf[K_CB * C_];
__device__ int g_ccount[N_TOK];
__device__ int g_cand[N_TOK * CAP];

// ---------------- helpers ---------------------------------------------------
__device__ __forceinline__ uint32_t smem_u32(const void* p) {
    uint32_t a;
    asm("{ .reg .u64 t; cvta.to.shared.u64 t, %1; cvt.u32.u64 %0, t; }" : "=r"(a) : "l"(p));
    return a;
}
__device__ __forceinline__ unsigned encf(float f) {
    unsigned u = __float_as_uint(f);
    return (u & 0x80000000u) ? ~u : (u | 0x80000000u);
}
__device__ __forceinline__ float decf(unsigned e) {
    unsigned u = (e & 0x80000000u) ? (e ^ 0x80000000u) : ~e;
    return __uint_as_float(u);
}
#define LDM_X4(r0, r1, r2, r3, a) \
    asm volatile("ldmatrix.sync.aligned.m8n8.x4.shared.b16 {%0,%1,%2,%3}, [%4];" \
                 : "=r"(r0), "=r"(r1), "=r"(r2), "=r"(r3) : "r"(a))
#define MMA16816(c, a, b0, b1) \
    asm volatile("mma.sync.aligned.m16n8k16.row.col.f32.bf16.bf16.f32 " \
                 "{%0,%1,%2,%3}, {%4,%5,%6,%7}, {%8,%9}, {%0,%1,%2,%3};" \
                 : "+f"((c)[0]), "+f"((c)[1]), "+f"((c)[2]), "+f"((c)[3]) \
                 : "r"((a)[0]), "r"((a)[1]), "r"((a)[2]), "r"((a)[3]), "r"(b0), "r"(b1))

// ---------------------------------------------------------------------------
__global__ void k_transpose(const float* __restrict__ z) {
    __shared__ float s[32][33];
    int cb = blockIdx.x, h = blockIdx.y, b = blockIdx.z;
    int tx = threadIdx.x, ty = threadIdx.y;
    s[ty][tx] = z[((b * C_ + cb * 32 + ty) * 32 + h) * 32 + tx];
    __syncthreads();
    float v = s[tx][ty];
    int idx = (b * 1024 + h * 32 + ty) * C_ + cb * 32 + tx;
    g_zflat[idx] = v;
    g_zbf[idx] = __float2bfloat16_rn(v);
}

__global__ void k_e2_init(const float* __restrict__ cbook) {
    int tid = threadIdx.x;
    int gid = blockIdx.x * 256 + tid;
    if (gid < N_TOK) { g_min[gid] = ~0ull; g_ccount[gid] = 0; }
    int k = blockIdx.x * 8 + (tid >> 5), lane = tid & 31;
    float s = 0.f;
#pragma unroll
    for (int j = 0; j < 8; j++) {
        float v = cbook[k * C_ + lane + j * 32];
        g_cbbf[k * C_ + lane + j * 32] = __float2bfloat16_rn(v);
        s += v * v;
    }
    for (int o = 16; o; o >>= 1) s += __shfl_down_sync(0xffffffffu, s, o);
    if (lane == 0) g_e2[k] = s;
}

__global__ void k_z2() {
    int tid = threadIdx.x;
    int tok = blockIdx.x * 8 + (tid >> 5), lane = tid & 31;
    float s = 0.f;
#pragma unroll
    for (int j = 0; j < 8; j++) { float v = g_zflat[tok * C_ + lane + j * 32]; s += v * v; }
    for (int o = 16; o; o >>= 1) s += __shfl_down_sync(0xffffffffu, s, o);
    if (lane == 0) g_z2[tok] = s;
}

// ---------------------------------------------------------------------------
// Filter GEMM via mma.sync bf16: per CTA 128 tokens vs 8192 codes (32x256).
// smem layout (dynamic): A[128][264] bf16 @0, B[256][264] bf16 @67584,
//                        e2s[256] f32 @202752, rm[128] u32 @203776.
// ---------------------------------------------------------------------------
#define ASTRIDE 528u            // 264 bf16 per row (8-half pad: conflict-free)
#define OFF_A   0u
#define OFF_B   67584u
#define OFF_E2  202752u
#define OFF_RM  203776u
#define SM_TOT  204288u

__global__ __launch_bounds__(256, 1) void k_gemm() {
    extern __shared__ char smem[];
    uint32_t sb = smem_u32(smem);
    int tid = threadIdx.x, wid = tid >> 5, lane = tid & 31;
    int g = lane >> 2, tg = lane & 3;
    int wm = wid >> 2, wn = wid & 3;          // 2 x 4 warp grid
    int m0 = blockIdx.x * 128;
    float*    e2s = (float*)(smem + OFF_E2);
    unsigned* rm  = (unsigned*)(smem + OFF_RM);

    // load A tile (128 x 256 bf16), plain row layout with padded stride
    for (int i = tid; i < 4096; i += 256) {
        int row = i >> 5, c8 = (i & 31) * 8;
        *(uint4*)(smem + OFF_A + row * ASTRIDE + c8 * 2) =
            *(const uint4*)&g_zbf[(m0 + row) * C_ + c8];
    }
    if (tid < 128) rm[tid] = 0xFFFFFFFFu;

    // per-lane ldmatrix A address base: matrices (m0-7,k0-7),(m8-15,k0-7),(m0-7,k8-15),(m8-15,k8-15)
    int arow = (lane & 7) + ((lane >> 3) & 1) * 8;
    int akb  = (lane >> 4) & 1;
    uint32_t aBase = sb + OFF_A + (uint32_t)(wm * 64 + arow) * ASTRIDE + (uint32_t)akb * 16;
    // per-lane B scalar base: row = wn*64 + g, col halves = tg*2
    uint32_t bLane = OFF_B + (uint32_t)(wn * 64 + g) * ASTRIDE + (uint32_t)tg * 4;

    for (int chunk = 0; chunk < 32; chunk++) {
        __syncthreads();   // protect B/e2s from pass2 readers of previous chunk
        // load B chunk (256 codes x 256 bf16) + e2
        for (int i = tid; i < 8192; i += 256) {
            int row = i >> 5, c8 = (i & 31) * 8;
            *(uint4*)(smem + OFF_B + row * ASTRIDE + c8 * 2) =
                *(const uint4*)&g_cbbf[(chunk * 256 + row) * C_ + c8];
        }
        if (tid < 256) e2s[tid] = g_e2[chunk * 256 + tid];
        __syncthreads();

        float acc[4][8][4];
#pragma unroll
        for (int mt = 0; mt < 4; mt++)
#pragma unroll
            for (int nt = 0; nt < 8; nt++)
#pragma unroll
                for (int c = 0; c < 4; c++) acc[mt][nt][c] = 0.f;

#pragma unroll
        for (int ks = 0; ks < 16; ks++) {
            uint32_t a[4][4];
#pragma unroll
            for (int mt = 0; mt < 4; mt++)
                LDM_X4(a[mt][0], a[mt][1], a[mt][2], a[mt][3],
                       aBase + (uint32_t)(mt * 16) * ASTRIDE + (uint32_t)ks * 32);
#pragma unroll
            for (int nt = 0; nt < 8; nt++) {
                uint32_t boff = bLane + (uint32_t)(nt * 8) * ASTRIDE + (uint32_t)ks * 32;
                uint32_t b0 = *(const uint32_t*)(smem + boff);
                uint32_t b1 = *(const uint32_t*)(smem + boff + 16);
#pragma unroll
                for (int mt = 0; mt < 4; mt++) MMA16816(acc[mt][nt], a[mt], b0, b1);
            }
        }

        // pass 1: per-token chunk minima -> shared rm (order-preserving uint)
#pragma unroll
        for (int mt = 0; mt < 4; mt++) {
            unsigned e0 = 0xFFFFFFFFu, e1 = 0xFFFFFFFFu;
#pragma unroll
            for (int nt = 0; nt < 8; nt++) {
                int nl = wn * 64 + nt * 8 + tg * 2;
                float m00 = __fmaf_rn(-2.f, acc[mt][nt][0], e2s[nl]);
                float m01 = __fmaf_rn(-2.f, acc[mt][nt][1], e2s[nl + 1]);
                float m10 = __fmaf_rn(-2.f, acc[mt][nt][2], e2s[nl]);
                float m11 = __fmaf_rn(-2.f, acc[mt][nt][3], e2s[nl + 1]);
                e0 = min(e0, min(encf(m00), encf(m01)));
                e1 = min(e1, min(encf(m10), encf(m11)));
            }
            e0 = min(e0, __shfl_xor_sync(0xffffffffu, e0, 1));
            e0 = min(e0, __shfl_xor_sync(0xffffffffu, e0, 2));
            e1 = min(e1, __shfl_xor_sync(0xffffffffu, e1, 1));
            e1 = min(e1, __shfl_xor_sync(0xffffffffu, e1, 2));
            if (tg == 0) {
                atomicMin(&rm[wm * 64 + mt * 16 + g], e0);
                atomicMin(&rm[wm * 64 + mt * 16 + 8 + g], e1);
            }
        }
        __syncthreads();

        // pass 2: emit candidates within MARGIN of token min-so-far
#pragma unroll
        for (int mt = 0; mt < 4; mt++) {
            int r0 = wm * 64 + mt * 16 + g, r1 = r0 + 8;
            float th0 = decf(rm[r0]) + MARGIN;
            float th1 = decf(rm[r1]) + MARGIN;
            int tok0 = m0 + r0, tok1 = m0 + r1;
#pragma unroll
            for (int nt = 0; nt < 8; nt++) {
                int nl = wn * 64 + nt * 8 + tg * 2;
                int code = chunk * 256 + nl;
                float m00 = __fmaf_rn(-2.f, acc[mt][nt][0], e2s[nl]);
                float m01 = __fmaf_rn(-2.f, acc[mt][nt][1], e2s[nl + 1]);
                float m10 = __fmaf_rn(-2.f, acc[mt][nt][2], e2s[nl]);
                float m11 = __fmaf_rn(-2.f, acc[mt][nt][3], e2s[nl + 1]);
                if (m00 < th0) { int s = atomicAdd(&g_ccount[tok0], 1); if (s < CAP) g_cand[tok0 * CAP + s] = code; }
                if (m01 < th0) { int s = atomicAdd(&g_ccount[tok0], 1); if (s < CAP) g_cand[tok0 * CAP + s] = code + 1; }
                if (m10 < th1) { int s = atomicAdd(&g_ccount[tok1], 1); if (s < CAP) g_cand[tok1 * CAP + s] = code; }
                if (m11 < th1) { int s = atomicAdd(&g_ccount[tok1], 1); if (s < CAP) g_cand[tok1 * CAP + s] = code + 1; }
            }
        }
    }
}

// ---------------------------------------------------------------------------
// Exact rescue: block per token, warp per candidate (fp32, R2 numerics)
// ---------------------------------------------------------------------------
__global__ __launch_bounds__(256, 4) void k_exact(const float* __restrict__ cbook) {
    __shared__ float zrow[256];
    int tok = blockIdx.x;
    int tid = threadIdx.x, wid = tid >> 5, lane = tid & 31;
    zrow[tid] = g_zflat[tok * C_ + tid];
    int cnt = g_ccount[tok]; if (cnt > CAP) cnt = CAP;
    float z2 = g_z2[tok];
    __syncthreads();
    for (int slot = wid; slot < cnt; slot += 8) {
        int code = g_cand[tok * CAP + slot];
        float s = 0.f;
#pragma unroll
        for (int j = 0; j < 8; j++)
            s += zrow[lane + 32 * j] * cbook[code * C_ + lane + 32 * j];
        for (int o = 16; o; o >>= 1) s += __shfl_down_sync(0xffffffffu, s, o);
        if (lane == 0) {
            float sz = __fadd_rn(z2, g_e2[code]);
            float d = __fadd_rn(sz, -2.0f * s);
            unsigned long long p = ((unsigned long long)__float_as_uint(d) << 32) | (unsigned)code;
            atomicMin(&g_min[tok], p);
        }
    }
}

// ---------------------------------------------------------------------------
__global__ void k_output(const float* __restrict__ cbook, float* __restrict__ out) {
    __shared__ float srow[256];
    __shared__ double sred[256];
    int t = threadIdx.x, bw = blockIdx.x;
    int b = bw >> 5, w = bw & 31;
    int gam = t & 7, h = t >> 3;
    double local = 0.0;
    for (int q = 0; q < 32; q++) {
        int np = b * 1024 + w * 32 + q;
        unsigned idx = (unsigned)(g_min[np] & 0xffffffffu);
        __syncthreads();
        srow[t] = cbook[idx * C_ + t];
        __syncthreads();
        int c = q * 8 + gam, cc = (gam << 5) | h;
        float zq = srow[cc];
        float zp = g_zflat[(b * 1024 + h * 32 + w) * C_ + c];
        out[((b * 32 + h) * 32 + w) * C_ + c] = zq;
        float df = zp - zq;
        local += (double)df * (double)df;
    }
    sred[t] = local;
    __syncthreads();
    for (int o = 128; o; o >>= 1) { if (t < o) sred[t] += sred[t + o]; __syncthreads(); }
    if (t == 0) g_partial[bw] = sred[0];
}

__global__ void k_final(float* __restrict__ out, int has_loss, int has_idx) {
    __shared__ double sr[256];
    int t = threadIdx.x, gid = blockIdx.x * 256 + t;
    if (has_idx && gid < N_TOK)
        out[ZQ_ELEMS + 1 + gid] = (float)(unsigned)(g_min[gid] & 0xffffffffu);
    if (has_loss && blockIdx.x == 0) {
        sr[t] = g_partial[t] + g_partial[t + 256];
        __syncthreads();
        for (int o = 128; o; o >>= 1) { if (t < o) sr[t] += sr[t + o]; __syncthreads(); }
        if (t == 0) out[ZQ_ELEMS] = (float)(1.25 * sr[0] / (double)ZQ_ELEMS);
    }
}

// ---------------------------------------------------------------------------
extern "C" void kernel_launch(void* const* d_in, const int* in_sizes, int n_in,
                              void* d_out, int out_size) {
    const float* z  = (const float*)d_in[0];
    const float* cb = (const float*)d_in[1];
    float* out = (float*)d_out;

    cudaFuncSetAttribute(k_gemm, cudaFuncAttributeMaxDynamicSharedMemorySize, SM_TOT);

    k_transpose<<<dim3(8, 32, 16), dim3(32, 32)>>>(z);
    k_e2_init<<<1024, 256>>>(cb);
    k_z2<<<2048, 256>>>();
    k_gemm<<<128, 256, SM_TOT>>>();
    k_exact<<<N_TOK, 256>>>(cb);
    if (out_size >= ZQ_ELEMS) k_output<<<512, 256>>>(cb, out);
    int has_loss = (out_size >= ZQ_ELEMS + 1) ? 1 : 0;
    int has_idx  = (out_size >= ZQ_ELEMS + 1 + N_TOK) ? 1 : 0;
    k_final<<<64, 256>>>(out, has_loss, has_idx);
}

// round 10
// speedup vs baseline: 3.4357x; 1.0428x over previous
#include <cuda_runtime.h>
#include <cuda_bf16.h>
#include <cstdint>

#define C_    256
#define N_TOK 16384
#define K_CB  8192
#define ZQ_ELEMS 4194304
#define CAP   512
#define MARGIN 4e-4f

// ---------------- scratch ---------------------------------------------------
__device__ float g_zflat[N_TOK * C_];
__device__ float g_z2[N_TOK];
__device__ float g_e2[K_CB];
__device__ unsigned long long g_min[N_TOK];
__device__ double g_partial[512];
__device__ __nv_bfloat16 g_zbf[N_TOK * C_];
__device__ __nv_bfloat16 g_cbbf[K_CB * C_];
__device__ int g_ccount[N_TOK];
__device__ int g_cand[N_TOK * CAP];

// ---------------- helpers ---------------------------------------------------
__device__ __forceinline__ uint32_t smem_u32(const void* p) {
    uint32_t a;
    asm("{ .reg .u64 t; cvta.to.shared.u64 t, %1; cvt.u32.u64 %0, t; }" : "=r"(a) : "l"(p));
    return a;
}
__device__ __forceinline__ unsigned encf(float f) {
    unsigned u = __float_as_uint(f);
    return (u & 0x80000000u) ? ~u : (u | 0x80000000u);
}
__device__ __forceinline__ float decf(unsigned e) {
    unsigned u = (e & 0x80000000u) ? (e ^ 0x80000000u) : ~e;
    return __uint_as_float(u);
}
#define LDM_X4(r0, r1, r2, r3, a) \
    asm volatile("ldmatrix.sync.aligned.m8n8.x4.shared.b16 {%0,%1,%2,%3}, [%4];" \
                 : "=r"(r0), "=r"(r1), "=r"(r2), "=r"(r3) : "r"(a))
#define MMA16816(c, a, b0, b1) \
    asm volatile("mma.sync.aligned.m16n8k16.row.col.f32.bf16.bf16.f32 " \
                 "{%0,%1,%2,%3}, {%4,%5,%6,%7}, {%8,%9}, {%0,%1,%2,%3};" \
                 : "+f"((c)[0]), "+f"((c)[1]), "+f"((c)[2]), "+f"((c)[3]) \
                 : "r"((a)[0]), "r"((a)[1]), "r"((a)[2]), "r"((a)[3]), "r"(b0), "r"(b1))
#define CP_ASYNC16(dst, src) \
    asm volatile("cp.async.cg.shared.global [%0], [%1], 16;" :: "r"(dst), "l"(src) : "memory")
#define CP_COMMIT() asm volatile("cp.async.commit_group;" ::: "memory")
#define CP_WAIT(n)  asm volatile("cp.async.wait_group %0;" :: "n"(n) : "memory")

// ---------------------------------------------------------------------------
__global__ void k_transpose(const float* __restrict__ z) {
    __shared__ float s[32][33];
    int cb = blockIdx.x, h = blockIdx.y, b = blockIdx.z;
    int tx = threadIdx.x, ty = threadIdx.y;
    s[ty][tx] = z[((b * C_ + cb * 32 + ty) * 32 + h) * 32 + tx];
    __syncthreads();
    float v = s[tx][ty];
    int idx = (b * 1024 + h * 32 + ty) * C_ + cb * 32 + tx;
    g_zflat[idx] = v;
    g_zbf[idx] = __float2bfloat16_rn(v);
}

__global__ void k_e2_init(const float* __restrict__ cbook) {
    int tid = threadIdx.x;
    int gid = blockIdx.x * 256 + tid;
    if (gid < N_TOK) { g_min[gid] = ~0ull; g_ccount[gid] = 0; }
    int k = blockIdx.x * 8 + (tid >> 5), lane = tid & 31;
    float s = 0.f;
#pragma unroll
    for (int j = 0; j < 8; j++) {
        float v = cbook[k * C_ + lane + j * 32];
        g_cbbf[k * C_ + lane + j * 32] = __float2bfloat16_rn(v);
        s += v * v;
    }
    for (int o = 16; o; o >>= 1) s += __shfl_down_sync(0xffffffffu, s, o);
    if (lane == 0) g_e2[k] = s;
}

__global__ void k_z2() {
    int tid = threadIdx.x;
    int tok = blockIdx.x * 8 + (tid >> 5), lane = tid & 31;
    float s = 0.f;
#pragma unroll
    for (int j = 0; j < 8; j++) { float v = g_zflat[tok * C_ + lane + j * 32]; s += v * v; }
    for (int o = 16; o; o >>= 1) s += __shfl_down_sync(0xffffffffu, s, o);
    if (lane == 0) g_z2[tok] = s;
}

// ---------------------------------------------------------------------------
// Filter GEMM: per CTA 128 tokens vs 8192 codes, 64 chunks of 128 codes,
// cp.async double-buffered B, 512 threads (4x4 warp grid, 32x32 warp tile).
// smem: A[128][264]bf16 @0, B0 @67584, B1 @135168 (each 128x264 bf16),
//       e2s[2][128] f32 @202752, rm[128] u32 @203776.
// ---------------------------------------------------------------------------
#define ASTRIDE 528u
#define OFF_A   0u
#define OFF_B0  67584u
#define OFF_B1  135168u
#define OFF_E2  202752u
#define OFF_RM  203776u
#define SM_TOT  204288u

__global__ __launch_bounds__(512, 1) void k_gemm() {
    extern __shared__ char smem[];
    uint32_t sb = smem_u32(smem);
    int tid = threadIdx.x, wid = tid >> 5, lane = tid & 31;
    int g = lane >> 2, tg = lane & 3;
    int wm = wid >> 2, wn = wid & 3;          // 4 x 4 warp grid
    int m0 = blockIdx.x * 128;
    float*    e2s = (float*)(smem + OFF_E2);
    unsigned* rm  = (unsigned*)(smem + OFF_RM);

    // A tile (128 x 256 bf16) + B chunk 0 via cp.async, one commit group
    for (int i = tid; i < 4096; i += 512) {
        int row = i >> 5, c8 = (i & 31) * 8;
        CP_ASYNC16(sb + OFF_A + row * ASTRIDE + c8 * 2, &g_zbf[(m0 + row) * C_ + c8]);
        CP_ASYNC16(sb + OFF_B0 + row * ASTRIDE + c8 * 2, &g_cbbf[row * C_ + c8]);
    }
    CP_COMMIT();
    if (tid < 128) { rm[tid] = 0xFFFFFFFFu; e2s[tid] = g_e2[tid]; }

    int arow = (lane & 7) + ((lane >> 3) & 1) * 8;
    int akb  = (lane >> 4) & 1;
    uint32_t aBase = sb + OFF_A + (uint32_t)(wm * 32 + arow) * ASTRIDE + (uint32_t)akb * 16;
    uint32_t bLane = (uint32_t)(wn * 32 + g) * ASTRIDE + (uint32_t)tg * 4;

    for (int chunk = 0; chunk < 64; chunk++) {
        int buf = chunk & 1;
        uint32_t bOff = buf ? OFF_B1 : OFF_B0;
        // prefetch next chunk into alternate buffer, then wait for current
        if (chunk < 63) {
            uint32_t nOff = buf ? OFF_B0 : OFF_B1;
            int n1 = (chunk + 1) * 128;
            for (int i = tid; i < 4096; i += 512) {
                int row = i >> 5, c8 = (i & 31) * 8;
                CP_ASYNC16(sb + nOff + row * ASTRIDE + c8 * 2, &g_cbbf[(n1 + row) * C_ + c8]);
            }
            if (tid < 128) e2s[(buf ^ 1) * 128 + tid] = g_e2[n1 + tid];
            CP_COMMIT();
            CP_WAIT(1);
        } else {
            CP_WAIT(0);
        }
        __syncthreads();

        float acc[2][4][4];
#pragma unroll
        for (int mt = 0; mt < 2; mt++)
#pragma unroll
            for (int nt = 0; nt < 4; nt++)
#pragma unroll
                for (int c = 0; c < 4; c++) acc[mt][nt][c] = 0.f;

#pragma unroll
        for (int ks = 0; ks < 16; ks++) {
            uint32_t a[2][4];
#pragma unroll
            for (int mt = 0; mt < 2; mt++)
                LDM_X4(a[mt][0], a[mt][1], a[mt][2], a[mt][3],
                       aBase + (uint32_t)(mt * 16) * ASTRIDE + (uint32_t)ks * 32);
#pragma unroll
            for (int nt = 0; nt < 4; nt++) {
                uint32_t boff = bOff + bLane + (uint32_t)(nt * 8) * ASTRIDE + (uint32_t)ks * 32;
                uint32_t b0 = *(const uint32_t*)(smem + boff);
                uint32_t b1 = *(const uint32_t*)(smem + boff + 16);
#pragma unroll
                for (int mt = 0; mt < 2; mt++) MMA16816(acc[mt][nt], a[mt], b0, b1);
            }
        }

        // pass 1: per-token chunk minima -> rm (order-preserving uint, monotone)
#pragma unroll
        for (int mt = 0; mt < 2; mt++) {
            unsigned e0 = 0xFFFFFFFFu, e1 = 0xFFFFFFFFu;
#pragma unroll
            for (int nt = 0; nt < 4; nt++) {
                int nl = wn * 32 + nt * 8 + tg * 2;
                float m00 = __fmaf_rn(-2.f, acc[mt][nt][0], e2s[buf * 128 + nl]);
                float m01 = __fmaf_rn(-2.f, acc[mt][nt][1], e2s[buf * 128 + nl + 1]);
                float m10 = __fmaf_rn(-2.f, acc[mt][nt][2], e2s[buf * 128 + nl]);
                float m11 = __fmaf_rn(-2.f, acc[mt][nt][3], e2s[buf * 128 + nl + 1]);
                e0 = min(e0, min(encf(m00), encf(m01)));
                e1 = min(e1, min(encf(m10), encf(m11)));
            }
            e0 = min(e0, __shfl_xor_sync(0xffffffffu, e0, 1));
            e0 = min(e0, __shfl_xor_sync(0xffffffffu, e0, 2));
            e1 = min(e1, __shfl_xor_sync(0xffffffffu, e1, 1));
            e1 = min(e1, __shfl_xor_sync(0xffffffffu, e1, 2));
            if (tg == 0) {
                atomicMin(&rm[wm * 32 + mt * 16 + g], e0);
                atomicMin(&rm[wm * 32 + mt * 16 + 8 + g], e1);
            }
        }
        __syncthreads();

        // pass 2: emit candidates within MARGIN of token min-so-far
#pragma unroll
        for (int mt = 0; mt < 2; mt++) {
            int r0 = wm * 32 + mt * 16 + g, r1 = r0 + 8;
            float th0 = decf(rm[r0]) + MARGIN;
            float th1 = decf(rm[r1]) + MARGIN;
            int tok0 = m0 + r0, tok1 = m0 + r1;
#pragma unroll
            for (int nt = 0; nt < 4; nt++) {
                int nl = wn * 32 + nt * 8 + tg * 2;
                int code = chunk * 128 + nl;
                float m00 = __fmaf_rn(-2.f, acc[mt][nt][0], e2s[buf * 128 + nl]);
                float m01 = __fmaf_rn(-2.f, acc[mt][nt][1], e2s[buf * 128 + nl + 1]);
                float m10 = __fmaf_rn(-2.f, acc[mt][nt][2], e2s[buf * 128 + nl]);
                float m11 = __fmaf_rn(-2.f, acc[mt][nt][3], e2s[buf * 128 + nl + 1]);
                if (m00 < th0) { int s = atomicAdd(&g_ccount[tok0], 1); if (s < CAP) g_cand[tok0 * CAP + s] = code; }
                if (m01 < th0) { int s = atomicAdd(&g_ccount[tok0], 1); if (s < CAP) g_cand[tok0 * CAP + s] = code + 1; }
                if (m10 < th1) { int s = atomicAdd(&g_ccount[tok1], 1); if (s < CAP) g_cand[tok1 * CAP + s] = code; }
                if (m11 < th1) { int s = atomicAdd(&g_ccount[tok1], 1); if (s < CAP) g_cand[tok1 * CAP + s] = code + 1; }
            }
        }
        __syncthreads();   // rm/e2s/B-buffer reuse fence for next chunk
    }
}

// ---------------------------------------------------------------------------
// Exact rescue: block per token, warp per candidate (fp32, R2 numerics)
// ---------------------------------------------------------------------------
__global__ __launch_bounds__(256, 4) void k_exact(const float* __restrict__ cbook) {
    __shared__ float zrow[256];
    int tok = blockIdx.x;
    int tid = threadIdx.x, wid = tid >> 5, lane = tid & 31;
    zrow[tid] = g_zflat[tok * C_ + tid];
    int cnt = g_ccount[tok]; if (cnt > CAP) cnt = CAP;
    float z2 = g_z2[tok];
    __syncthreads();
    for (int slot = wid; slot < cnt; slot += 8) {
        int code = g_cand[tok * CAP + slot];
        float s = 0.f;
#pragma unroll
        for (int j = 0; j < 8; j++)
            s += zrow[lane + 32 * j] * cbook[code * C_ + lane + 32 * j];
        for (int o = 16; o; o >>= 1) s += __shfl_down_sync(0xffffffffu, s, o);
        if (lane == 0) {
            float sz = __fadd_rn(z2, g_e2[code]);
            float d = __fadd_rn(sz, -2.0f * s);
            unsigned long long p = ((unsigned long long)__float_as_uint(d) << 32) | (unsigned)code;
            atomicMin(&g_min[tok], p);
        }
    }
}

// ---------------------------------------------------------------------------
__global__ void k_output(const float* __restrict__ cbook, float* __restrict__ out) {
    __shared__ float srow[256];
    __shared__ double sred[256];
    int t = threadIdx.x, bw = blockIdx.x;
    int b = bw >> 5, w = bw & 31;
    int gam = t & 7, h = t >> 3;
    double local = 0.0;
    for (int q = 0; q < 32; q++) {
        int np = b * 1024 + w * 32 + q;
        unsigned idx = (unsigned)(g_min[np] & 0xffffffffu);
        __syncthreads();
        srow[t] = cbook[idx * C_ + t];
        __syncthreads();
        int c = q * 8 + gam, cc = (gam << 5) | h;
        float zq = srow[cc];
        float zp = g_zflat[(b * 1024 + h * 32 + w) * C_ + c];
        out[((b * 32 + h) * 32 + w) * C_ + c] = zq;
        float df = zp - zq;
        local += (double)df * (double)df;
    }
    sred[t] = local;
    __syncthreads();
    for (int o = 128; o; o >>= 1) { if (t < o) sred[t] += sred[t + o]; __syncthreads(); }
    if (t == 0) g_partial[bw] = sred[0];
}

__global__ void k_final(float* __restrict__ out, int has_loss, int has_idx) {
    __shared__ double sr[256];
    int t = threadIdx.x, gid = blockIdx.x * 256 + t;
    if (has_idx && gid < N_TOK)
        out[ZQ_ELEMS + 1 + gid] = (float)(unsigned)(g_min[gid] & 0xffffffffu);
    if (has_loss && blockIdx.x == 0) {
        sr[t] = g_partial[t] + g_partial[t + 256];
        __syncthreads();
        for (int o = 128; o; o >>= 1) { if (t < o) sr[t] += sr[t + o]; __syncthreads(); }
        if (t == 0) out[ZQ_ELEMS] = (float)(1.25 * sr[0] / (double)ZQ_ELEMS);
    }
}

// ---------------------------------------------------------------------------
extern "C" void kernel_launch(void* const* d_in, const int* in_sizes, int n_in,
                              void* d_out, int out_size) {
    const float* z  = (const float*)d_in[0];
    const float* cb = (const float*)d_in[1];
    float* out = (float*)d_out;

    cudaFuncSetAttribute(k_gemm, cudaFuncAttributeMaxDynamicSharedMemorySize, SM_TOT);

    k_transpose<<<dim3(8, 32, 16), dim3(32, 32)>>>(z);
    k_e2_init<<<1024, 256>>>(cb);
    k_z2<<<2048, 256>>>();
    k_gemm<<<128, 512, SM_TOT>>>();
    k_exact<<<N_TOK, 256>>>(cb);
    if (out_size >= ZQ_ELEMS) k_output<<<512, 256>>>(cb, out);
    int has_loss = (out_size >= ZQ_ELEMS + 1) ? 1 : 0;
    int has_idx  = (out_size >= ZQ_ELEMS + 1 + N_TOK) ? 1 : 0;
    k_final<<<64, 256>>>(out, has_loss, has_idx);
}

// round 11
// speedup vs baseline: 3.5815x; 1.0424x over previous
#include <cuda_runtime.h>
#include <cuda_bf16.h>
#include <cstdint>

#define C_    256
#define N_TOK 16384
#define K_CB  8192
#define ZQ_ELEMS 4194304
#define CAP   512
#define MARGIN 4e-4f

// ---------------- scratch ---------------------------------------------------
__device__ float g_zflat[N_TOK * C_];
__device__ float g_e2[K_CB];
__device__ unsigned long long g_min[N_TOK];
__device__ double g_partial[512];
__device__ __nv_bfloat16 g_zbf[N_TOK * C_];
__device__ __nv_bfloat16 g_cbbf[K_CB * C_];
__device__ int g_ccount[N_TOK];
__device__ int g_cand[N_TOK * CAP];

// ---------------- helpers ---------------------------------------------------
__device__ __forceinline__ uint32_t smem_u32(const void* p) {
    uint32_t a;
    asm("{ .reg .u64 t; cvta.to.shared.u64 t, %1; cvt.u32.u64 %0, t; }" : "=r"(a) : "l"(p));
    return a;
}
__device__ __forceinline__ unsigned encf(float f) {
    unsigned u = __float_as_uint(f);
    return (u & 0x80000000u) ? ~u : (u | 0x80000000u);
}
__device__ __forceinline__ float decf(unsigned e) {
    unsigned u = (e & 0x80000000u) ? (e ^ 0x80000000u) : ~e;
    return __uint_as_float(u);
}
#define LDM_X4(r0, r1, r2, r3, a) \
    asm volatile("ldmatrix.sync.aligned.m8n8.x4.shared.b16 {%0,%1,%2,%3}, [%4];" \
                 : "=r"(r0), "=r"(r1), "=r"(r2), "=r"(r3) : "r"(a))
#define MMA16816(c, a, b0, b1) \
    asm volatile("mma.sync.aligned.m16n8k16.row.col.f32.bf16.bf16.f32 " \
                 "{%0,%1,%2,%3}, {%4,%5,%6,%7}, {%8,%9}, {%0,%1,%2,%3};" \
                 : "+f"((c)[0]), "+f"((c)[1]), "+f"((c)[2]), "+f"((c)[3]) \
                 : "r"((a)[0]), "r"((a)[1]), "r"((a)[2]), "r"((a)[3]), "r"(b0), "r"(b1))
#define CP_ASYNC16(dst, src) \
    asm volatile("cp.async.cg.shared.global [%0], [%1], 16;" :: "r"(dst), "l"(src) : "memory")
#define CP_COMMIT() asm volatile("cp.async.commit_group;" ::: "memory")
#define CP_WAIT(n)  asm volatile("cp.async.wait_group %0;" :: "n"(n) : "memory")

// ---------------------------------------------------------------------------
__global__ void k_transpose(const float* __restrict__ z) {
    __shared__ float s[32][33];
    int cb = blockIdx.x, h = blockIdx.y, b = blockIdx.z;
    int tx = threadIdx.x, ty = threadIdx.y;
    s[ty][tx] = z[((b * C_ + cb * 32 + ty) * 32 + h) * 32 + tx];
    __syncthreads();
    float v = s[tx][ty];
    int idx = (b * 1024 + h * 32 + ty) * C_ + cb * 32 + tx;
    g_zflat[idx] = v;
    g_zbf[idx] = __float2bfloat16_rn(v);
}

__global__ void k_e2_init(const float* __restrict__ cbook) {
    int tid = threadIdx.x;
    int gid = blockIdx.x * 256 + tid;
    if (gid < N_TOK) { g_min[gid] = ~0ull; g_ccount[gid] = 0; }
    int k = blockIdx.x * 8 + (tid >> 5), lane = tid & 31;
    float s = 0.f;
#pragma unroll
    for (int j = 0; j < 8; j++) {
        float v = cbook[k * C_ + lane + j * 32];
        g_cbbf[k * C_ + lane + j * 32] = __float2bfloat16_rn(v);
        s += v * v;
    }
    for (int o = 16; o; o >>= 1) s += __shfl_down_sync(0xffffffffu, s, o);
    if (lane == 0) g_e2[k] = s;
}

// ---------------------------------------------------------------------------
// Filter GEMM: per CTA 128 tokens vs 8192 codes, 64 chunks of 128 codes,
// cp.async double-buffered B, 512 threads (4x4 warp grid, 32x32 warp tile).
// A and B fragments both via ldmatrix.x4; epilogue in-place, 2 barriers/chunk.
// ---------------------------------------------------------------------------
#define ASTRIDE 528u
#define OFF_A   0u
#define OFF_B0  67584u
#define OFF_B1  135168u
#define OFF_E2  202752u
#define OFF_RM  203776u
#define SM_TOT  204288u

__global__ __launch_bounds__(512, 1) void k_gemm() {
    extern __shared__ char smem[];
    uint32_t sb = smem_u32(smem);
    int tid = threadIdx.x, wid = tid >> 5, lane = tid & 31;
    int g = lane >> 2, tg = lane & 3;
    int wm = wid >> 2, wn = wid & 3;          // 4 x 4 warp grid
    int m0 = blockIdx.x * 128;
    float*    e2s = (float*)(smem + OFF_E2);
    unsigned* rm  = (unsigned*)(smem + OFF_RM);

    // A tile (128 x 256 bf16) + B chunk 0 via cp.async, one commit group
    for (int i = tid; i < 4096; i += 512) {
        int row = i >> 5, c8 = (i & 31) * 8;
        CP_ASYNC16(sb + OFF_A + row * ASTRIDE + c8 * 2, &g_zbf[(m0 + row) * C_ + c8]);
        CP_ASYNC16(sb + OFF_B0 + row * ASTRIDE + c8 * 2, &g_cbbf[row * C_ + c8]);
    }
    CP_COMMIT();
    if (tid < 128) { rm[tid] = 0xFFFFFFFFu; e2s[tid] = g_e2[tid]; }

    // A ldmatrix lane address
    int arow = (lane & 7) + ((lane >> 3) & 1) * 8;
    int akb  = (lane >> 4) & 1;
    uint32_t aBase = sb + OFF_A + (uint32_t)(wm * 32 + arow) * ASTRIDE + (uint32_t)akb * 16;
    // B ldmatrix lane address: m8n8.x4 covers n16 x k16 (two n8 tiles)
    int brow = lane & 7;
    int bk   = (lane >> 3) & 1;
    int bn8  = (lane >> 4) & 1;
    uint32_t bBase = sb + (uint32_t)(wn * 32 + bn8 * 8 + brow) * ASTRIDE + (uint32_t)bk * 16;

    for (int chunk = 0; chunk < 64; chunk++) {
        int buf = chunk & 1;
        uint32_t bOff = buf ? OFF_B1 : OFF_B0;
        if (chunk < 63) {
            uint32_t nOff = buf ? OFF_B0 : OFF_B1;
            int n1 = (chunk + 1) * 128;
            for (int i = tid; i < 4096; i += 512) {
                int row = i >> 5, c8 = (i & 31) * 8;
                CP_ASYNC16(sb + nOff + row * ASTRIDE + c8 * 2, &g_cbbf[(n1 + row) * C_ + c8]);
            }
            if (tid < 128) e2s[(buf ^ 1) * 128 + tid] = g_e2[n1 + tid];
            CP_COMMIT();
            CP_WAIT(1);
        } else {
            CP_WAIT(0);
        }
        __syncthreads();

        float acc[2][4][4];
#pragma unroll
        for (int mt = 0; mt < 2; mt++)
#pragma unroll
            for (int nt = 0; nt < 4; nt++)
#pragma unroll
                for (int c = 0; c < 4; c++) acc[mt][nt][c] = 0.f;

#pragma unroll
        for (int ks = 0; ks < 16; ks++) {
            uint32_t a[2][4];
#pragma unroll
            for (int mt = 0; mt < 2; mt++)
                LDM_X4(a[mt][0], a[mt][1], a[mt][2], a[mt][3],
                       aBase + (uint32_t)(mt * 16) * ASTRIDE + (uint32_t)ks * 32);
            uint32_t b[2][4];
#pragma unroll
            for (int nt2 = 0; nt2 < 2; nt2++)
                LDM_X4(b[nt2][0], b[nt2][1], b[nt2][2], b[nt2][3],
                       bBase + bOff + (uint32_t)(nt2 * 16) * ASTRIDE + (uint32_t)ks * 32);
#pragma unroll
            for (int nt2 = 0; nt2 < 2; nt2++)
#pragma unroll
                for (int mt = 0; mt < 2; mt++) {
                    MMA16816(acc[mt][nt2 * 2],     a[mt], b[nt2][0], b[nt2][1]);
                    MMA16816(acc[mt][nt2 * 2 + 1], a[mt], b[nt2][2], b[nt2][3]);
                }
        }

        // epilogue: m = fma(-2, acc, e2) in place (computed once)
#pragma unroll
        for (int mt = 0; mt < 2; mt++)
#pragma unroll
            for (int nt = 0; nt < 4; nt++) {
                int nl = buf * 128 + wn * 32 + nt * 8 + tg * 2;
                float e0 = e2s[nl], e1 = e2s[nl + 1];
                acc[mt][nt][0] = __fmaf_rn(-2.f, acc[mt][nt][0], e0);
                acc[mt][nt][1] = __fmaf_rn(-2.f, acc[mt][nt][1], e1);
                acc[mt][nt][2] = __fmaf_rn(-2.f, acc[mt][nt][2], e0);
                acc[mt][nt][3] = __fmaf_rn(-2.f, acc[mt][nt][3], e1);
            }

        // pass 1: per-token chunk minima -> rm (monotone atomicMin on enc floats)
#pragma unroll
        for (int mt = 0; mt < 2; mt++) {
            unsigned e0 = 0xFFFFFFFFu, e1 = 0xFFFFFFFFu;
#pragma unroll
            for (int nt = 0; nt < 4; nt++) {
                e0 = min(e0, min(encf(acc[mt][nt][0]), encf(acc[mt][nt][1])));
                e1 = min(e1, min(encf(acc[mt][nt][2]), encf(acc[mt][nt][3])));
            }
            e0 = min(e0, __shfl_xor_sync(0xffffffffu, e0, 1));
            e0 = min(e0, __shfl_xor_sync(0xffffffffu, e0, 2));
            e1 = min(e1, __shfl_xor_sync(0xffffffffu, e1, 1));
            e1 = min(e1, __shfl_xor_sync(0xffffffffu, e1, 2));
            if (tg == 0) {
                atomicMin(&rm[wm * 32 + mt * 16 + g], e0);
                atomicMin(&rm[wm * 32 + mt * 16 + 8 + g], e1);
            }
        }
        // only chunk 0 needs its own minima visible (cold start); later chunks'
        // thresholds from earlier chunks are already safe (rm >= rm_final).
        if (chunk == 0) __syncthreads();

        // pass 2: emit candidates within MARGIN of token min-so-far
#pragma unroll
        for (int mt = 0; mt < 2; mt++) {
            int r0 = wm * 32 + mt * 16 + g, r1 = r0 + 8;
            float th0 = decf(rm[r0]) + MARGIN;
            float th1 = decf(rm[r1]) + MARGIN;
            int tok0 = m0 + r0, tok1 = m0 + r1;
#pragma unroll
            for (int nt = 0; nt < 4; nt++) {
                int code = chunk * 128 + wn * 32 + nt * 8 + tg * 2;
                if (acc[mt][nt][0] < th0) { int s = atomicAdd(&g_ccount[tok0], 1); if (s < CAP) g_cand[tok0 * CAP + s] = code; }
                if (acc[mt][nt][1] < th0) { int s = atomicAdd(&g_ccount[tok0], 1); if (s < CAP) g_cand[tok0 * CAP + s] = code + 1; }
                if (acc[mt][nt][2] < th1) { int s = atomicAdd(&g_ccount[tok1], 1); if (s < CAP) g_cand[tok1 * CAP + s] = code; }
                if (acc[mt][nt][3] < th1) { int s = atomicAdd(&g_ccount[tok1], 1); if (s < CAP) g_cand[tok1 * CAP + s] = code + 1; }
            }
        }
        __syncthreads();   // protects B buffer reuse + e2s halves across chunks
    }
}

// ---------------------------------------------------------------------------
// Exact rescue: block per token, warp per candidate (fp32, R2 numerics).
// z2 computed in-kernel with the exact same lane/shfl order as the old k_z2.
// ---------------------------------------------------------------------------
__global__ __launch_bounds__(256, 4) void k_exact(const float* __restrict__ cbook) {
    __shared__ float zrow[256];
    int tok = blockIdx.x;
    int tid = threadIdx.x, wid = tid >> 5, lane = tid & 31;
    zrow[tid] = g_zflat[tok * C_ + tid];
    int cnt = g_ccount[tok]; if (cnt > CAP) cnt = CAP;
    __syncthreads();
    float z2 = 0.f;
#pragma unroll
    for (int j = 0; j < 8; j++) { float v = zrow[lane + 32 * j]; z2 += v * v; }
    for (int o = 16; o; o >>= 1) z2 += __shfl_down_sync(0xffffffffu, z2, o);
    for (int slot = wid; slot < cnt; slot += 8) {
        int code = g_cand[tok * CAP + slot];
        float s = 0.f;
#pragma unroll
        for (int j = 0; j < 8; j++)
            s += zrow[lane + 32 * j] * cbook[code * C_ + lane + 32 * j];
        for (int o = 16; o; o >>= 1) s += __shfl_down_sync(0xffffffffu, s, o);
        if (lane == 0) {
            float sz = __fadd_rn(z2, g_e2[code]);
            float d = __fadd_rn(sz, -2.0f * s);
            unsigned long long p = ((unsigned long long)__float_as_uint(d) << 32) | (unsigned)code;
            atomicMin(&g_min[tok], p);
        }
    }
}

// ---------------------------------------------------------------------------
__global__ void k_output(const float* __restrict__ cbook, float* __restrict__ out) {
    __shared__ float srow[256];
    __shared__ double sred[256];
    int t = threadIdx.x, bw = blockIdx.x;
    int b = bw >> 5, w = bw & 31;
    int gam = t & 7, h = t >> 3;
    double local = 0.0;
    for (int q = 0; q < 32; q++) {
        int np = b * 1024 + w * 32 + q;
        unsigned idx = (unsigned)(g_min[np] & 0xffffffffu);
        __syncthreads();
        srow[t] = cbook[idx * C_ + t];
        __syncthreads();
        int c = q * 8 + gam, cc = (gam << 5) | h;
        float zq = srow[cc];
        float zp = g_zflat[(b * 1024 + h * 32 + w) * C_ + c];
        out[((b * 32 + h) * 32 + w) * C_ + c] = zq;
        float df = zp - zq;
        local += (double)df * (double)df;
    }
    sred[t] = local;
    __syncthreads();
    for (int o = 128; o; o >>= 1) { if (t < o) sred[t] += sred[t + o]; __syncthreads(); }
    if (t == 0) g_partial[bw] = sred[0];
}

__global__ void k_final(float* __restrict__ out, int has_loss, int has_idx) {
    __shared__ double sr[256];
    int t = threadIdx.x, gid = blockIdx.x * 256 + t;
    if (has_idx && gid < N_TOK)
        out[ZQ_ELEMS + 1 + gid] = (float)(unsigned)(g_min[gid] & 0xffffffffu);
    if (has_loss && blockIdx.x == 0) {
        sr[t] = g_partial[t] + g_partial[t + 256];
        __syncthreads();
        for (int o = 128; o; o >>= 1) { if (t < o) sr[t] += sr[t + o]; __syncthreads(); }
        if (t == 0) out[ZQ_ELEMS] = (float)(1.25 * sr[0] / (double)ZQ_ELEMS);
    }
}

// ---------------------------------------------------------------------------
extern "C" void kernel_launch(void* const* d_in, const int* in_sizes, int n_in,
                              void* d_out, int out_size) {
    const float* z  = (const float*)d_in[0];
    const float* cb = (const float*)d_in[1];
    float* out = (float*)d_out;

    cudaFuncSetAttribute(k_gemm, cudaFuncAttributeMaxDynamicSharedMemorySize, SM_TOT);

    k_transpose<<<dim3(8, 32, 16), dim3(32, 32)>>>(z);
    k_e2_init<<<1024, 256>>>(cb);
    k_gemm<<<128, 512, SM_TOT>>>();
    k_exact<<<N_TOK, 256>>>(cb);
    if (out_size >= ZQ_ELEMS) k_output<<<512, 256>>>(cb, out);
    int has_loss = (out_size >= ZQ_ELEMS + 1) ? 1 : 0;
    int has_idx  = (out_size >= ZQ_ELEMS + 1 + N_TOK) ? 1 : 0;
    k_final<<<64, 256>>>(out, has_loss, has_idx);
}